// round 1
// baseline (speedup 1.0000x reference)
#include <cuda_runtime.h>
#include <math.h>

#define D       64
#define KMAX    1024
#define TN      128
#define TK      128
#define NROWS   131072
#define XNUMEL  8388608
#define XS_STRIDE 132   // 128 + 4 pad, keeps 16B alignment

// Scratch (no allocations allowed): codes transposed [d][k], half-norms, histogram, per-block SSE partials
__device__ float g_codesT[D * KMAX];
__device__ float g_hn[KMAX];
__device__ int   g_hist[KMAX];
__device__ float g_partial[1024];

// ---------------------------------------------------------------------------
// Prep: gather codebook (emb0 | emb1/emb2 per idx) into transposed scratch,
// compute 0.5*||c||^2, mask invalid codes (idx==0 -> only 512 valid), zero hist.
// ---------------------------------------------------------------------------
__global__ void vq_prep(const float* __restrict__ e0, const float* __restrict__ e1,
                        const float* __restrict__ e2, const int* __restrict__ idxp)
{
    int k = blockIdx.x;       // 0..1023
    int d = threadIdx.x;      // 0..63
    int idx = *idxp;

    const float* src = e0 + k * D;
    bool valid = true;
    if (k >= 512) {
        if (idx == 1)      src = e1 + (k - 512) * D;
        else if (idx >= 2) src = e2 + (k - 512) * D;
        else               valid = false;   // idx==0: only emb0
    }
    float v = valid ? src[d] : 0.0f;
    g_codesT[d * KMAX + k] = v;

    float s = v * v;
    #pragma unroll
    for (int o = 16; o > 0; o >>= 1) s += __shfl_down_sync(0xffffffffu, s, o);
    __shared__ float wsum[2];
    if ((threadIdx.x & 31) == 0) wsum[threadIdx.x >> 5] = s;
    __syncthreads();
    if (threadIdx.x == 0) {
        float tot = wsum[0] + wsum[1];
        g_hn[k]   = valid ? 0.5f * tot : 1e30f;  // invalid codes can never win argmax
        g_hist[k] = 0;
    }
}

// ---------------------------------------------------------------------------
// Main: per 128-row tile, argmax_k (x.c - 0.5||c||^2) over 1024 codes in 8
// chunks of 128 (smem), 8x8 fp32 register microtile per thread. Fused
// epilogue: quantized NCHW write + SSE partial + histogram.
// ---------------------------------------------------------------------------
__global__ void __launch_bounds__(256) vq_main(const float* __restrict__ x,
                                               float* __restrict__ out)
{
    extern __shared__ float sm[];
    float* x_s  = sm;                       // [64][132]
    float* c_s  = sm + D * XS_STRIDE;       // [64][132]
    float* hn_s = sm + 2 * D * XS_STRIDE;   // [128]

    const int t   = threadIdx.x;
    const int n0  = blockIdx.x * TN;
    const int b   = n0 >> 12;               // 4096 spatial positions per image
    const int hw0 = n0 & 4095;
    const float* xbase = x + (size_t)b * 262144 + hw0;

    // Load X tile: x[b, d, hw0 + r] -> x_s[d][r], fully coalesced float4
    #pragma unroll
    for (int k = 0; k < 8; ++k) {
        int i  = t + k * 256;
        int d  = i >> 5;
        int rq = i & 31;
        float4 v = *(const float4*)(xbase + d * 4096 + rq * 4);
        *(float4*)(x_s + d * XS_STRIDE + rq * 4) = v;
    }

    const int ty = t >> 4, tx = t & 15;
    float best[8];
    int   bidx[8];
    #pragma unroll
    for (int i = 0; i < 8; ++i) { best[i] = -3.0e38f; bidx[i] = 0; }

    for (int ch = 0; ch < 8; ++ch) {
        __syncthreads();   // protect c_s from previous chunk's readers
        #pragma unroll
        for (int k = 0; k < 8; ++k) {
            int i  = t + k * 256;
            int d  = i >> 5;
            int kq = i & 31;
            float4 v = *(const float4*)(g_codesT + d * KMAX + ch * TK + kq * 4);
            *(float4*)(c_s + d * XS_STRIDE + kq * 4) = v;
        }
        if (t < 128) hn_s[t] = g_hn[ch * TK + t];
        __syncthreads();

        float acc[8][8];
        #pragma unroll
        for (int i = 0; i < 8; ++i)
            #pragma unroll
            for (int j = 0; j < 8; ++j) acc[i][j] = 0.0f;

        #pragma unroll 8
        for (int d = 0; d < D; ++d) {
            float4 xa = *(const float4*)(x_s + d * XS_STRIDE + ty * 8);
            float4 xb = *(const float4*)(x_s + d * XS_STRIDE + ty * 8 + 4);
            float4 ca = *(const float4*)(c_s + d * XS_STRIDE + tx * 8);
            float4 cb = *(const float4*)(c_s + d * XS_STRIDE + tx * 8 + 4);
            float xr[8] = {xa.x, xa.y, xa.z, xa.w, xb.x, xb.y, xb.z, xb.w};
            float cr[8] = {ca.x, ca.y, ca.z, ca.w, cb.x, cb.y, cb.z, cb.w};
            #pragma unroll
            for (int i = 0; i < 8; ++i)
                #pragma unroll
                for (int j = 0; j < 8; ++j)
                    acc[i][j] = fmaf(xr[i], cr[j], acc[i][j]);
        }

        // scores + running argmax (ascending k within thread -> strict > keeps
        // first index, matching jnp.argmin tie-break)
        #pragma unroll
        for (int i = 0; i < 8; ++i)
            #pragma unroll
            for (int j = 0; j < 8; ++j) {
                float s = acc[i][j] - hn_s[tx * 8 + j];
                int  kk = ch * TK + tx * 8 + j;
                if (s > best[i]) { best[i] = s; bidx[i] = kk; }
            }
    }

    // Cross-thread (16 tx) reduction per row, explicit index tie-break
    __syncthreads();
    float* redS = c_s;                  // [128][16]
    int*   redI = (int*)(c_s + 2048);   // [128][16]
    #pragma unroll
    for (int i = 0; i < 8; ++i) {
        int r = ty * 8 + i;
        redS[r * 16 + tx] = best[i];
        redI[r * 16 + tx] = bidx[i];
    }
    __syncthreads();
    int* bestrow = (int*)hn_s;          // reuse, hn no longer needed
    if (t < 128) {
        float bs = -3.0e38f; int bi = 0x7fffffff;
        #pragma unroll
        for (int q = 0; q < 16; ++q) {
            float s = redS[t * 16 + q];
            int  kk = redI[t * 16 + q];
            if (s > bs || (s == bs && kk < bi)) { bs = s; bi = kk; }
        }
        bestrow[t] = bi;
        atomicAdd(&g_hist[bi], 1);
    }
    __syncthreads();

    // Epilogue: quantized write (coalesced along spatial r) + SSE
    float lsse = 0.0f;
    float* outb = out + (size_t)b * 262144 + hw0;
    #pragma unroll
    for (int k = 0; k < 32; ++k) {
        int e = t + k * 256;
        int c = e >> 7, r = e & 127;
        float q  = g_codesT[c * KMAX + bestrow[r]];   // L2-resident gather
        float xv = x_s[c * XS_STRIDE + r];
        float dd = q - xv;
        lsse += dd * dd;
        outb[c * 4096 + r] = q;
    }

    // Deterministic block reduction of SSE -> per-block partial (no float atomics)
    __syncthreads();
    float* rr = c_s;
    rr[t] = lsse;
    __syncthreads();
    for (int o = 128; o > 0; o >>= 1) {
        if (t < o) rr[t] += rr[t + o];
        __syncthreads();
    }
    if (t == 0) g_partial[blockIdx.x] = rr[0];
}

// ---------------------------------------------------------------------------
// Final: loss = 1.25 * mean((q-x)^2); perplexity = exp(-sum p log(p+eps))
// ---------------------------------------------------------------------------
__global__ void vq_final(float* __restrict__ out, int xnumel)
{
    __shared__ float sred[1024];
    int t = threadIdx.x;

    sred[t] = g_partial[t];
    __syncthreads();
    for (int o = 512; o > 0; o >>= 1) { if (t < o) sred[t] += sred[t + o]; __syncthreads(); }
    float sse = sred[0];
    __syncthreads();

    float p = (float)g_hist[t] * (1.0f / (float)NROWS);
    sred[t] = p * logf(p + 1e-10f);   // 0 * log(eps) == 0 for empty bins, matches ref
    __syncthreads();
    for (int o = 512; o > 0; o >>= 1) { if (t < o) sred[t] += sred[t + o]; __syncthreads(); }

    if (t == 0) {
        out[xnumel]     = 1.25f * sse / (float)XNUMEL;  // q_loss + 0.25*e_loss (numerically equal)
        out[xnumel + 1] = expf(-sred[0]);
    }
}

// ---------------------------------------------------------------------------
extern "C" void kernel_launch(void* const* d_in, const int* in_sizes, int n_in,
                              void* d_out, int out_size)
{
    const float* x    = (const float*)d_in[0];
    const float* e0   = (const float*)d_in[1];
    const float* e1   = (const float*)d_in[2];
    const float* e2   = (const float*)d_in[3];
    const int*   idxp = (const int*)d_in[4];
    float* out = (float*)d_out;
    int xnumel = in_sizes[0];

    size_t smem = (2 * D * XS_STRIDE + 128) * sizeof(float);  // 68096 B
    cudaFuncSetAttribute(vq_main, cudaFuncAttributeMaxDynamicSharedMemorySize, (int)smem);

    vq_prep<<<KMAX, D>>>(e0, e1, e2, idxp);
    vq_main<<<NROWS / TN, 256, smem>>>(x, out);
    vq_final<<<1, 1024>>>(out, xnumel);
}

// round 3
// speedup vs baseline: 1.0085x; 1.0085x over previous
#include <cuda_runtime.h>
#include <math.h>

#define D       64
#define KMAX    1024
#define TN      128
#define TK      128
#define NROWS   131072
#define XNUMEL  8388608
#define XS_STRIDE 132   // 128 + 4 pad, keeps 16B alignment

// Scratch (no allocations allowed)
__device__ float g_codesT[D * KMAX];   // [d][k]  for GEMM tiles
__device__ float g_codesR[KMAX * D];   // [k][d]  for coalesced epilogue gather
__device__ float g_hn[KMAX];
__device__ int   g_hist[KMAX];
__device__ float g_partial[1024];

// ---- packed f32x2 helpers (Blackwell FFMA2 — only reachable via PTX) -------
#define PACK2BC(out, a)   asm("mov.b64 %0, {%1, %1};" : "=l"(out) : "f"(a))
#define FMA2(acc, x, c)   asm("fma.rn.f32x2 %0, %1, %2, %3;" : "=l"(acc) : "l"(x), "l"(c), "l"(acc))
#define UNPACK2(lo, hi, p) asm("mov.b64 {%0, %1}, %2;" : "=f"(lo), "=f"(hi) : "l"(p))

// ---------------------------------------------------------------------------
// Prep: gather codebook into transposed + row-major scratch, 0.5*||c||^2,
// mask invalid codes (idx==0 -> only 512 valid), zero histogram.
// ---------------------------------------------------------------------------
__global__ void vq_prep(const float* __restrict__ e0, const float* __restrict__ e1,
                        const float* __restrict__ e2, const int* __restrict__ idxp)
{
    int k = blockIdx.x * blockDim.y + threadIdx.y;  // code id
    int d = threadIdx.x;                            // 0..63
    int idx = *idxp;

    const float* src = e0 + k * D;
    bool valid = true;
    if (k >= 512) {
        if (idx == 1)      src = e1 + (k - 512) * D;
        else if (idx >= 2) src = e2 + (k - 512) * D;
        else               valid = false;
    }
    float v = valid ? src[d] : 0.0f;
    g_codesT[d * KMAX + k] = v;
    g_codesR[k * D + d]    = v;

    float s = v * v;
    #pragma unroll
    for (int o = 16; o > 0; o >>= 1) s += __shfl_down_sync(0xffffffffu, s, o);
    __shared__ float wsum[4][2];
    if ((d & 31) == 0) wsum[threadIdx.y][d >> 5] = s;
    __syncthreads();
    if (d == 0) {
        float tot = wsum[threadIdx.y][0] + wsum[threadIdx.y][1];
        g_hn[k]   = valid ? 0.5f * tot : 1e30f;
        g_hist[k] = 0;
    }
}

// ---------------------------------------------------------------------------
// Main: argmax_k (x.c - 0.5||c||^2), 128-row x 1024-code per CTA, 8 chunks of
// 128 codes, 8x8 microtile computed as 8x4 packed f32x2 FMAs.
// ---------------------------------------------------------------------------
__global__ void __launch_bounds__(256, 2) vq_main(const float* __restrict__ x,
                                                  float* __restrict__ out)
{
    extern __shared__ float sm[];
    float* x_s  = sm;                       // [64][132]
    float* c_s  = sm + D * XS_STRIDE;       // [64][132]  (reused later)
    float* hn_s = sm + 2 * D * XS_STRIDE;   // [128]

    const int t   = threadIdx.x;
    const int n0  = blockIdx.x * TN;
    const int b   = n0 >> 12;               // 4096 spatial positions per image
    const int hw0 = n0 & 4095;
    const float* xbase = x + (size_t)b * 262144 + hw0;

    // X tile: x[b, d, hw0+r] -> x_s[d][r], coalesced float4
    #pragma unroll
    for (int k = 0; k < 8; ++k) {
        int i  = t + k * 256;
        int d  = i >> 5;
        int rq = i & 31;
        float4 v = *(const float4*)(xbase + d * 4096 + rq * 4);
        *(float4*)(x_s + d * XS_STRIDE + rq * 4) = v;
    }

    const int ty = t >> 4, tx = t & 15;
    float best[8];
    int   bidx[8];
    #pragma unroll
    for (int i = 0; i < 8; ++i) { best[i] = -3.0e38f; bidx[i] = 0; }

    for (int ch = 0; ch < 8; ++ch) {
        __syncthreads();   // protect c_s from previous chunk's readers
        #pragma unroll
        for (int k = 0; k < 8; ++k) {
            int i  = t + k * 256;
            int d  = i >> 5;
            int kq = i & 31;
            float4 v = *(const float4*)(g_codesT + d * KMAX + ch * TK + kq * 4);
            *(float4*)(c_s + d * XS_STRIDE + kq * 4) = v;
        }
        if (t < 128) hn_s[t] = g_hn[ch * TK + t];
        __syncthreads();

        unsigned long long acc[8][4];
        #pragma unroll
        for (int i = 0; i < 8; ++i)
            #pragma unroll
            for (int jp = 0; jp < 4; ++jp) acc[i][jp] = 0ull;

        #pragma unroll 8
        for (int d = 0; d < D; ++d) {
            const float* xrow = x_s + d * XS_STRIDE + ty * 8;
            float4 xa = *(const float4*)xrow;
            float4 xb = *(const float4*)(xrow + 4);
            unsigned long long xp[8];
            PACK2BC(xp[0], xa.x); PACK2BC(xp[1], xa.y);
            PACK2BC(xp[2], xa.z); PACK2BC(xp[3], xa.w);
            PACK2BC(xp[4], xb.x); PACK2BC(xp[5], xb.y);
            PACK2BC(xp[6], xb.z); PACK2BC(xp[7], xb.w);

            const ulonglong2* crow = (const ulonglong2*)(c_s + d * XS_STRIDE + tx * 8);
            ulonglong2 ca = crow[0];          // codes (tx*8+0, +1), (+2, +3)
            ulonglong2 cb = crow[1];          // codes (+4, +5), (+6, +7)
            unsigned long long cp[4] = {ca.x, ca.y, cb.x, cb.y};

            #pragma unroll
            for (int i = 0; i < 8; ++i) {
                FMA2(acc[i][0], xp[i], cp[0]);
                FMA2(acc[i][1], xp[i], cp[1]);
                FMA2(acc[i][2], xp[i], cp[2]);
                FMA2(acc[i][3], xp[i], cp[3]);
            }
        }

        // scores + running argmax (ascending k, strict > keeps first index ->
        // matches jnp.argmin tie-break)
        #pragma unroll
        for (int i = 0; i < 8; ++i)
            #pragma unroll
            for (int jp = 0; jp < 4; ++jp) {
                float s0, s1;
                UNPACK2(s0, s1, acc[i][jp]);
                int kbase = ch * TK + tx * 8 + jp * 2;
                s0 -= hn_s[tx * 8 + jp * 2];
                s1 -= hn_s[tx * 8 + jp * 2 + 1];
                if (s0 > best[i]) { best[i] = s0; bidx[i] = kbase; }
                if (s1 > best[i]) { best[i] = s1; bidx[i] = kbase + 1; }
            }
    }

    // Cross-thread (16 tx) reduction per row, explicit index tie-break
    __syncthreads();
    float* redS = c_s;                  // [128][16]
    int*   redI = (int*)(c_s + 2048);   // [128][16]
    #pragma unroll
    for (int i = 0; i < 8; ++i) {
        int r = ty * 8 + i;
        redS[r * 16 + tx] = best[i];
        redI[r * 16 + tx] = bidx[i];
    }
    __syncthreads();
    int* bestrow = (int*)hn_s;          // reuse
    if (t < 128) {
        float bs = -3.0e38f; int bi = 0x7fffffff;
        #pragma unroll
        for (int q = 0; q < 16; ++q) {
            float s = redS[t * 16 + q];
            int  kk = redI[t * 16 + q];
            if (s > bs || (s == bs && kk < bi)) { bs = s; bi = kk; }
        }
        bestrow[t] = bi;
        atomicAdd(&g_hist[bi], 1);
    }
    __syncthreads();

    // Epilogue phase 1: coalesced row-major gather of winning codes -> smem
    // transpose staging (c_s as [c][r]) + SSE accumulation.
    float lsse = 0.0f;
    #pragma unroll
    for (int k = 0; k < 32; ++k) {
        int e = t + k * 256;
        int r = e >> 6, c = e & 63;           // c fastest -> coalesced gather
        float q  = g_codesR[bestrow[r] * D + c];
        float xv = x_s[c * XS_STRIDE + r];
        float dd = q - xv;
        lsse += dd * dd;
        c_s[c * XS_STRIDE + r] = q;
    }
    __syncthreads();

    // Epilogue phase 2: coalesced NCHW store (r fastest within each channel)
    float* outb = out + (size_t)b * 262144 + hw0;
    #pragma unroll
    for (int k = 0; k < 8; ++k) {
        int i  = t + k * 256;
        int c  = i >> 5;
        int rq = i & 31;
        float4 v = *(const float4*)(c_s + c * XS_STRIDE + rq * 4);
        *(float4*)(outb + c * 4096 + rq * 4) = v;
    }

    // Deterministic block reduction of SSE
    __syncthreads();
    float* rr = c_s;
    rr[t] = lsse;
    __syncthreads();
    for (int o = 128; o > 0; o >>= 1) {
        if (t < o) rr[t] += rr[t + o];
        __syncthreads();
    }
    if (t == 0) g_partial[blockIdx.x] = rr[0];
}

// ---------------------------------------------------------------------------
// Final: loss = 1.25 * mean((q-x)^2); perplexity = exp(-sum p log(p+eps))
// ---------------------------------------------------------------------------
__global__ void vq_final(float* __restrict__ out, int xnumel)
{
    __shared__ float sred[1024];
    int t = threadIdx.x;

    sred[t] = g_partial[t];
    __syncthreads();
    for (int o = 512; o > 0; o >>= 1) { if (t < o) sred[t] += sred[t + o]; __syncthreads(); }
    float sse = sred[0];
    __syncthreads();

    float p = (float)g_hist[t] * (1.0f / (float)NROWS);
    sred[t] = p * logf(p + 1e-10f);
    __syncthreads();
    for (int o = 512; o > 0; o >>= 1) { if (t < o) sred[t] += sred[t + o]; __syncthreads(); }

    if (t == 0) {
        out[xnumel]     = 1.25f * sse / (float)XNUMEL;
        out[xnumel + 1] = expf(-sred[0]);
    }
}

// ---------------------------------------------------------------------------
extern "C" void kernel_launch(void* const* d_in, const int* in_sizes, int n_in,
                              void* d_out, int out_size)
{
    const float* x    = (const float*)d_in[0];
    const float* e0   = (const float*)d_in[1];
    const float* e1   = (const float*)d_in[2];
    const float* e2   = (const float*)d_in[3];
    const int*   idxp = (const int*)d_in[4];
    float* out = (float*)d_out;
    int xnumel = in_sizes[0];

    size_t smem = (2 * D * XS_STRIDE + 128) * sizeof(float);  // 68096 B
    cudaFuncSetAttribute(vq_main, cudaFuncAttributeMaxDynamicSharedMemorySize, (int)smem);

    dim3 pb(64, 4);
    vq_prep<<<KMAX / 4, pb>>>(e0, e1, e2, idxp);
    vq_main<<<NROWS / TN, 256, smem>>>(x, out);
    vq_final<<<1, 1024>>>(out, xnumel);
}